// round 11
// baseline (speedup 1.0000x reference)
#include <cuda_runtime.h>
#include <cstdint>

#define GRID_N   7
#define NB       2
#define NC       20
#define IS       8
#define DCH      30
#define L_BOX    5.0f
#define L_NEG    0.5f

#define TPB      256
#define WARPS    (TPB / 32)
#define MAX_BLOCKS 4096

__device__ double g_partials[MAX_BLOCKS];
__device__ unsigned int g_count = 0;

__device__ __forceinline__ void cp_async16(uint32_t dst, const void* src) {
    asm volatile("cp.async.cg.shared.global [%0], [%1], 16;\n" :: "r"(dst), "l"(src));
}
__device__ __forceinline__ void cp_commit() {
    asm volatile("cp.async.commit_group;\n" ::: "memory");
}
__device__ __forceinline__ void cp_wait0() {
    asm volatile("cp.async.wait_group 0;\n" ::: "memory");
}

__device__ __forceinline__ float bce_t(float x) {           // 1 + exp(-|x|)
    return 1.0f + __expf(-fabsf(x));
}

__device__ __forceinline__ float box_loss_f(const float* pb, const float* gb) {
    float dx = pb[0] - gb[0];
    float dy = pb[1] - gb[1];
    float sw = sqrtf(fabsf(pb[2])) - sqrtf(gb[2]);
    float sh = sqrtf(fabsf(pb[3])) - sqrtf(gb[3]);
    return dx * dx + dy * dy + sw * sw + sh * sh;
}

// box + conf part given registers (p box/conf + g box + conf_g). cls handled elsewhere.
__device__ __forceinline__ float boxconf_loss(const float pv[IS], const float gv[IS],
                                              float2 pconf, float conf_g, int cellIdx) {
    if (conf_g > 0.0f) {
        int cell = cellIdx % (GRID_N * GRID_N);
        float col = (float)(cell % GRID_N);
        float row = (float)(cell / GRID_N);

        float poff[NB][4], gbox[NB][4];
        #pragma unroll
        for (int b = 0; b < NB; b++) {
            poff[b][0] = __fdividef(1.0f, 1.0f + __expf(-pv[4 * b + 0]));
            poff[b][1] = __fdividef(1.0f, 1.0f + __expf(-pv[4 * b + 1]));
            poff[b][2] = pv[4 * b + 2];
            poff[b][3] = pv[4 * b + 3];
            gbox[b][0] = gv[4 * b + 0];
            gbox[b][1] = gv[4 * b + 1];
            gbox[b][2] = gv[4 * b + 2];
            gbox[b][3] = gv[4 * b + 3];
        }

        float pl[NB][4], gl[NB][4];
        #pragma unroll
        for (int b = 0; b < NB; b++) {
            float cx = (poff[b][0] + col) * (1.0f / GRID_N);
            float cy = (poff[b][1] + row) * (1.0f / GRID_N);
            float w  = poff[b][2], h = poff[b][3];
            pl[b][0] = cx - w * 0.5f; pl[b][1] = cy - h * 0.5f;
            pl[b][2] = cx + w * 0.5f; pl[b][3] = cy + h * 0.5f;
            float gx = (gbox[b][0] + col) * (1.0f / GRID_N);
            float gy = (gbox[b][1] + row) * (1.0f / GRID_N);
            float gw = gbox[b][2], gh = gbox[b][3];
            gl[b][0] = gx - gw * 0.5f; gl[b][1] = gy - gh * 0.5f;
            gl[b][2] = gx + gw * 0.5f; gl[b][3] = gy + gh * 0.5f;
        }

        float iou[NB][NB];
        #pragma unroll
        for (int pi = 0; pi < NB; pi++) {
            #pragma unroll
            for (int gi = 0; gi < NB; gi++) {
                float ltx = fmaxf(pl[pi][0], gl[gi][0]);
                float lty = fmaxf(pl[pi][1], gl[gi][1]);
                float rbx = fminf(pl[pi][2], gl[gi][2]);
                float rby = fminf(pl[pi][3], gl[gi][3]);
                float wx = fmaxf(rbx - ltx, 0.0f);
                float wy = fmaxf(rby - lty, 0.0f);
                float inter = wx * wy;
                float aa = (pl[pi][2] - pl[pi][0]) * (pl[pi][3] - pl[pi][1]);
                float ab = (gl[gi][2] - gl[gi][0]) * (gl[gi][3] - gl[gi][1]);
                iou[pi][gi] = __fdividef(inter, aa + ab - inter + 1e-7f);
            }
        }

        int ind0 = (iou[1][0] > iou[0][0]) ? 1 : 0;
        int ind1 = (iou[1][1] > iou[0][1]) ? 1 : 0;

        bool same_g = (gbox[0][0] == gbox[1][0]) && (gbox[0][1] == gbox[1][1]) &&
                      (gbox[0][2] == gbox[1][2]) && (gbox[0][3] == gbox[1][3]);
        bool same_ind = (ind0 == ind1);

        float box_cell;
        if (same_g) {
            box_cell = box_loss_f(poff[ind0], gbox[0]);
        } else if (same_ind) {
            box_cell = box_loss_f(poff[0], gbox[0]) + box_loss_f(poff[1], gbox[1]);
        } else {
            box_cell = box_loss_f(poff[ind0], gbox[0]) + box_loss_f(poff[ind1], gbox[1]);
        }

        float conf_cell;
        if (same_g) {
            float x = ind1 ? pconf.y : pconf.x;
            conf_cell = fmaxf(x, 0.f) - x + __logf(bce_t(x));
        } else {
            conf_cell = fmaxf(pconf.x, 0.f) - pconf.x + fmaxf(pconf.y, 0.f) - pconf.y
                      + __logf(bce_t(pconf.x) * bce_t(pconf.y));
        }
        return L_BOX * box_cell + conf_cell;
    } else {
        return L_NEG * (fmaxf(pconf.x, 0.f) + fmaxf(pconf.y, 0.f)
                        + __logf(bce_t(pconf.x) * bce_t(pconf.y)));
    }
}

// full per-lane path (tail tiles only): everything direct from gmem, incl. cls.
__device__ __forceinline__ float cell_loss_direct(const float* __restrict__ pc,
                                                  const float* __restrict__ gc,
                                                  int cellIdx) {
    const float2* pc2 = reinterpret_cast<const float2*>(pc);
    const float2* gc2 = reinterpret_cast<const float2*>(gc);
    float2 pconf = pc2[4];
    float conf_g = gc2[4].x;

    float pv[IS], gv[IS];
    #pragma unroll
    for (int i = 0; i < 4; i++) {
        float2 a = pc2[i]; pv[2*i] = a.x; pv[2*i+1] = a.y;
        float2 b = gc2[i]; gv[2*i] = b.x; gv[2*i+1] = b.y;
    }

    float acc = boxconf_loss(pv, gv, pconf, conf_g, cellIdx);

    if (conf_g > 0.0f) {
        const float2* pcl2 = reinterpret_cast<const float2*>(pc + NB * 5);
        const float2* gcl2 = reinterpret_cast<const float2*>(gc + NB * 5);
        float lin = 0.0f, prod = 1.0f;
        #pragma unroll
        for (int i = 0; i < NC / 2; i++) {
            float2 a = pcl2[i];
            float2 b = gcl2[i];
            lin  += fmaxf(a.x, 0.f) - a.x * b.x + fmaxf(a.y, 0.f) - a.y * b.y;
            prod *= bce_t(a.x) * bce_t(a.y);
        }
        acc += lin + __logf(prod);
    }
    return acc;
}

__global__ void __launch_bounds__(TPB)
yolo_loss_kernel(const float* __restrict__ p, const float* __restrict__ g,
                 int ncells, float* __restrict__ out, float inv_nb) {
    // per-warp staged p tile: 32 cells x 30 floats = 240 float4 = 3840 B
    __shared__ float4 sP[WARPS][240];       // 8 * 3840 = 30720 B

    const int tid  = threadIdx.x;
    const int lane = tid & 31;
    const int wid  = tid >> 5;
    const int t    = blockIdx.x * WARPS + wid;   // this warp's tile
    const int c0   = t * 32;

    float acc = 0.0f;

    if (c0 + 32 <= ncells) {
        // ================== fast path: full 32-cell tile ==================
        // 1) stage p tile via cp.async (coalesced, 16B chunks)
        {
            const float4* src = reinterpret_cast<const float4*>(p + (size_t)c0 * DCH) + lane;
            uint32_t d = (uint32_t)__cvta_generic_to_shared(&sP[wid][0]) + lane * 16;
            #pragma unroll
            for (int k = 0; k < 7; k++)
                cp_async16(d + k * 512, src + 32 * k);
            if (lane < 16)
                cp_async16(d + 7 * 512, src + 224);
            cp_commit();
        }

        // 2) issue all g loads back-to-back (independent, MLP ~15)
        const int myCell = c0 + lane;
        const float* gcell = g + (size_t)myCell * DCH;
        const float2* gc2 = reinterpret_cast<const float2*>(gcell);
        float2 gB0 = gc2[0], gB1 = gc2[1], gB2 = gc2[2], gB3 = gc2[3];
        float  conf_g = __ldg(gcell + IS);

        // g cls, channel-parallel: element q = j*32+lane of tile's 320 float2 pairs
        const float2* gt2 = reinterpret_cast<const float2*>(g) + (size_t)t * 480;
        float2 gg[10];
        #pragma unroll
        for (int j = 0; j < 10; j++) {
            int q = j * 32 + lane;
            int cell = q / 10;
            int pair = q - cell * 10;
            gg[j] = __ldg(gt2 + cell * 15 + 5 + pair);
        }

        // 3) mask of positive cells in this tile (bit c = cell c0+c positive)
        unsigned mb = __ballot_sync(0xffffffffu, conf_g > 0.0f);

        // 4) wait for staged p
        cp_wait0();
        __syncwarp();

        // 5) cls: channel-parallel masked sum; p from smem (computed-address LDS)
        {
            const float2* sp2 = reinterpret_cast<const float2*>(&sP[wid][0]);
            float lin = 0.0f, prod = 1.0f;
            #pragma unroll
            for (int j = 0; j < 10; j++) {
                int q = j * 32 + lane;
                int cell = q / 10;
                int pair = q - cell * 10;
                float2 a = sp2[cell * 15 + 5 + pair];
                float2 b = gg[j];
                bool m = (mb >> cell) & 1u;
                float lq = fmaxf(a.x, 0.f) - a.x * b.x + fmaxf(a.y, 0.f) - a.y * b.y;
                float pq = bce_t(a.x) * bce_t(a.y);
                lin  += m ? lq : 0.0f;
                prod *= m ? pq : 1.0f;
            }
            acc += lin + __logf(prod);   // prod <= 2^10: safe
        }

        // 6) per-lane box/conf: p from smem, g from regs
        {
            const float* pvs = reinterpret_cast<const float*>(&sP[wid][0]) + lane * DCH;
            const float2* pv2 = reinterpret_cast<const float2*>(pvs);
            float2 pB0 = pv2[0], pB1 = pv2[1], pB2 = pv2[2], pB3 = pv2[3];
            float2 pconf = pv2[4];
            float pv[IS] = {pB0.x, pB0.y, pB1.x, pB1.y, pB2.x, pB2.y, pB3.x, pB3.y};
            float gv[IS] = {gB0.x, gB0.y, gB1.x, gB1.y, gB2.x, gB2.y, gB3.x, gB3.y};
            acc += boxconf_loss(pv, gv, pconf, conf_g, myCell);
        }
    } else if (c0 + lane < ncells) {
        // ================== tail: per-lane direct ==================
        int idx = c0 + lane;
        acc = cell_loss_direct(p + (size_t)idx * DCH, g + (size_t)idx * DCH, idx);
    }

    // ---- deterministic block reduction ----
    #pragma unroll
    for (int o = 16; o > 0; o >>= 1)
        acc += __shfl_down_sync(0xffffffffu, acc, o);

    __shared__ float warp_sums[WARPS];
    if (lane == 0) warp_sums[wid] = acc;
    __syncthreads();

    if (tid == 0) {
        float v = 0.0f;
        #pragma unroll
        for (int w = 0; w < WARPS; w++) v += warp_sums[w];
        g_partials[blockIdx.x] = (double)v;
    }

    // ---- last-block finalization (deterministic fixed-order sum) ----
    __shared__ bool isLast;
    if (tid == 0) {
        __threadfence();
        unsigned int v = atomicAdd(&g_count, 1u);
        isLast = (v == gridDim.x - 1);
    }
    __syncthreads();

    if (isLast) {
        __shared__ double sh[TPB];
        double s = 0.0;
        for (int i = tid; i < (int)gridDim.x; i += TPB)
            s += g_partials[i];
        sh[tid] = s;
        __syncthreads();
        #pragma unroll
        for (int strideR = TPB / 2; strideR > 0; strideR >>= 1) {
            if (tid < strideR) sh[tid] += sh[tid + strideR];
            __syncthreads();
        }
        if (tid == 0) {
            out[0] = (float)(sh[0] * (double)inv_nb);
            g_count = 0;   // reset for next graph replay
        }
    }
}

extern "C" void kernel_launch(void* const* d_in, const int* in_sizes, int n_in,
                              void* d_out, int out_size) {
    const float* p = (const float*)d_in[0];
    const float* g = (const float*)d_in[1];
    float* out = (float*)d_out;

    int ncells = in_sizes[0] / DCH;                 // B * 49
    int batch  = ncells / (GRID_N * GRID_N);        // B
    int warptiles = (ncells + 31) / 32;
    int nblocks = (warptiles + WARPS - 1) / WARPS;
    if (nblocks > MAX_BLOCKS) nblocks = MAX_BLOCKS; // never hit for this size

    yolo_loss_kernel<<<nblocks, TPB>>>(p, g, ncells, out, 1.0f / (float)batch);
}